// round 4
// baseline (speedup 1.0000x reference)
#include <cuda_runtime.h>
#include <math.h>

#define N 4096
#define F 512
#define O 64
#define H 8
#define C 16
#define NW 128  // mask words per row (N/32)

typedef unsigned long long ull;

// -------- scratch (static device globals; no allocation) --------
__device__ unsigned g_mask[N * NW];          // 2 MB bit-packed adjacency
__device__ float g_Wh[H * N * O];            // 8 MB
__device__ float2 g_E1pn[H * N];             // (exp(v1), exp(0.2 v1))
__device__ float2 g_E2pn[H * N];
__device__ float g_hcat[N * F];              // 8 MB  (F == H*O)
__device__ float g_Who[N * C];
__device__ float2 g2_E1pn[N], g2_E2pn[N];

// -------- f32x2 helpers --------
__device__ __forceinline__ ull fma2(ull a, ull b, ull c) {
    ull d; asm("fma.rn.f32x2 %0, %1, %2, %3;" : "=l"(d) : "l"(a), "l"(b), "l"(c)); return d;
}
__device__ __forceinline__ ull mul2(ull a, ull b) {
    ull d; asm("mul.rn.f32x2 %0, %1, %2;" : "=l"(d) : "l"(a), "l"(b)); return d;
}
__device__ __forceinline__ ull f2u(float2 f) {
    ull u; asm("mov.b64 %0, {%1,%2};" : "=l"(u) : "f"(f.x), "f"(f.y)); return u;
}
__device__ __forceinline__ float2 u2f(ull u) {
    float2 f; asm("mov.b64 {%0,%1}, %2;" : "=f"(f.x), "=f"(f.y) : "l"(u)); return f;
}

// ---------------- K0: pack adjacency to bits ----------------
__global__ void k_pack(const int* __restrict__ adj) {
    int gt = blockIdx.x * blockDim.x + threadIdx.x;
    int w = gt >> 5, lane = gt & 31;
    int i = w >> 7, jw = w & (NW - 1);
    int v = adj[i * N + jw * 32 + lane];
    unsigned m = __ballot_sync(0xffffffffu, v > 0);
    if (lane == 0) g_mask[w] = m;
}

// ---------------- K1: Wh[h] = x @ W[h]  via f32x2, pair-k ----------------
// grid (N/64, H), 128 threads: ty16 (4 rows) x tx8 (8 cols)
__global__ void __launch_bounds__(128, 4) k_gemm1(const float* __restrict__ x,
                                                  const float* __restrict__ W) {
    __shared__ float2 s_xs[64 * 35];   // xs[r][kp] = (x[r][2kp], x[r][2kp+1]), stride 35
    __shared__ float2 s_wi[32 * 80];   // wi[kp][slot]: col c at slot (c>>3)*10 + (c&7)
    int h = blockIdx.y;
    int r0 = blockIdx.x * 64;
    int t = threadIdx.x;
    int ty = t >> 3, tx = t & 7;
    int rbase = ty * 4;

    ull acc[4][8];
#pragma unroll
    for (int i = 0; i < 4; ++i)
#pragma unroll
        for (int c = 0; c < 8; ++c) acc[i][c] = 0ull;

    for (int k0 = 0; k0 < F; k0 += 64) {
        // load x tile: 64 rows x 64 k (16 float4 per row)
        for (int u = t; u < 1024; u += 128) {
            int r = u >> 4, kq = u & 15;
            float4 v = *(const float4*)&x[(r0 + r) * F + k0 + kq * 4];
            float2* d = &s_xs[r * 35 + kq * 2];
            d[0] = make_float2(v.x, v.y);
            d[1] = make_float2(v.z, v.w);
        }
        // load W tile, k-interleaved into padded groups (8B stores: always aligned)
        for (int u = t; u < 512; u += 128) {
            int kp = u >> 4, c4 = u & 15;
            const float* wb = W + (h * F + k0 + 2 * kp) * O + c4 * 4;
            float4 a = *(const float4*)wb;
            float4 b = *(const float4*)(wb + O);
            int g = c4 >> 1, off = (c4 & 1) * 4;
            float2* d = &s_wi[kp * 80 + g * 10 + off];
            d[0] = make_float2(a.x, b.x);
            d[1] = make_float2(a.y, b.y);
            d[2] = make_float2(a.z, b.z);
            d[3] = make_float2(a.w, b.w);
        }
        __syncthreads();
#pragma unroll 2
        for (int kp = 0; kp < 32; ++kp) {
            ull pr[4];
#pragma unroll
            for (int i = 0; i < 4; ++i)
                pr[i] = *(const ull*)&s_xs[(rbase + i) * 35 + kp];
            const ull* wp = (const ull*)&s_wi[kp * 80 + tx * 10];
            ull w[8];
#pragma unroll
            for (int c = 0; c < 8; ++c) w[c] = wp[c];
#pragma unroll
            for (int i = 0; i < 4; ++i)
#pragma unroll
                for (int c = 0; c < 8; ++c)
                    acc[i][c] = fma2(pr[i], w[c], acc[i][c]);
        }
        __syncthreads();
    }
#pragma unroll
    for (int i = 0; i < 4; ++i) {
        int row = r0 + rbase + i;
        float v[8];
#pragma unroll
        for (int c = 0; c < 8; ++c) { float2 f = u2f(acc[i][c]); v[c] = f.x + f.y; }
        float* dst = g_Wh + (h * N + row) * O + tx * 8;
        *(float4*)dst = make_float4(v[0], v[1], v[2], v[3]);
        *(float4*)(dst + 4) = make_float4(v[4], v[5], v[6], v[7]);
    }
}

// ---------------- K1b: per-node scores + factored exponentials (layer 1) ----------------
__global__ void k_scores1(const float* __restrict__ a) {
    int gw = (blockIdx.x * blockDim.x + threadIdx.x) >> 5;  // gw = h*N + n
    int lane = threadIdx.x & 31;
    int h = gw >> 12;
    const float* wh = g_Wh + gw * O;
    const float* ah = a + h * 2 * O;
    float w0 = wh[lane], w1 = wh[lane + 32];
    float v1 = w0 * ah[lane] + w1 * ah[lane + 32];
    float v2 = w0 * ah[O + lane] + w1 * ah[O + lane + 32];
#pragma unroll
    for (int off = 16; off; off >>= 1) {
        v1 += __shfl_down_sync(0xffffffffu, v1, off);
        v2 += __shfl_down_sync(0xffffffffu, v2, off);
    }
    if (lane == 0) {
        g_E1pn[gw] = make_float2(expf(v1), expf(0.2f * v1));
        g_E2pn[gw] = make_float2(expf(v2), expf(0.2f * v2));
    }
}

// ---------------- K2: layer-1 masked-softmax aggregate + ELU ----------------
// grid (N/64, H), 128 threads.
// Phase 1: weights once into P tile (64 x 64 per chunk). Phase 2: f32x2 GEMM.
__global__ void __launch_bounds__(128, 4) k_agg1() {
    __shared__ float2 s_whi[32 * 80];  // j-interleaved Wh tile, padded groups
    __shared__ float  s_pt[64 * 70];   // P tile, row stride 70
    __shared__ float  s_dp[64][2];
    int h = blockIdx.y;
    int hN = h * N;
    int r0 = blockIdx.x * 64;
    int t = threadIdx.x;
    int ty = t >> 3, tx = t & 7;
    int rbase = ty * 4;
    int rr = t >> 1, half = t & 1;     // phase-1 mapping

    ull e1u = f2u(g_E1pn[hN + r0 + rr]);
    float denl = 0.f;

    ull acc[4][8];
#pragma unroll
    for (int i = 0; i < 4; ++i)
#pragma unroll
        for (int c = 0; c < 8; ++c) acc[i][c] = 0ull;

    for (int j0 = 0; j0 < N; j0 += 64) {
        // phase 0: Wh tile, j-interleaved (8B stores: always aligned)
        for (int u = t; u < 512; u += 128) {
            int jp = u >> 4, c4 = u & 15;
            const float* wb = g_Wh + (hN + j0 + 2 * jp) * O + c4 * 4;
            float4 a = *(const float4*)wb;
            float4 b = *(const float4*)(wb + O);
            int g = c4 >> 1, off = (c4 & 1) * 4;
            float2* d = &s_whi[jp * 80 + g * 10 + off];
            d[0] = make_float2(a.x, b.x);
            d[1] = make_float2(a.y, b.y);
            d[2] = make_float2(a.z, b.z);
            d[3] = make_float2(a.w, b.w);
        }
        // phase 1: weights (each computed once)
        {
            unsigned m = g_mask[(r0 + rr) * NW + (j0 >> 5) + half];
            const float2* e2p = &g_E2pn[hN + j0 + half * 32];
#pragma unroll
            for (int jj = 0; jj < 32; jj += 2) {
                float2 fa = u2f(mul2(e1u, f2u(e2p[jj])));
                float2 fb = u2f(mul2(e1u, f2u(e2p[jj + 1])));
                float w0 = fmaxf(fa.x, fa.y);
                float w1 = fmaxf(fb.x, fb.y);
                w0 = ((m >> jj) & 1u) ? w0 : 0.f;
                w1 = ((m >> (jj + 1)) & 1u) ? w1 : 0.f;
                denl += w0 + w1;
                *(float2*)&s_pt[rr * 70 + half * 32 + jj] = make_float2(w0, w1);
            }
        }
        __syncthreads();
        // phase 2: acc += P @ Wh (f32x2, pair-j)
#pragma unroll 2
        for (int jp = 0; jp < 32; ++jp) {
            ull pr[4];
#pragma unroll
            for (int i = 0; i < 4; ++i)
                pr[i] = *(const ull*)&s_pt[(rbase + i) * 70 + 2 * jp];
            const ull* wp = (const ull*)&s_whi[jp * 80 + tx * 10];
            ull w[8];
#pragma unroll
            for (int c = 0; c < 8; ++c) w[c] = wp[c];
#pragma unroll
            for (int i = 0; i < 4; ++i)
#pragma unroll
                for (int c = 0; c < 8; ++c)
                    acc[i][c] = fma2(pr[i], w[c], acc[i][c]);
        }
        __syncthreads();
    }
    s_dp[rr][half] = denl;
    __syncthreads();
#pragma unroll
    for (int i = 0; i < 4; ++i) {
        int r = rbase + i;
        float inv = 1.f / (s_dp[r][0] + s_dp[r][1]);
        float v[8];
#pragma unroll
        for (int c = 0; c < 8; ++c) {
            float2 f = u2f(acc[i][c]);
            float s = (f.x + f.y) * inv;
            v[c] = (s > 0.f) ? s : (expf(s) - 1.f);
        }
        float* dst = g_hcat + (r0 + r) * F + h * O + tx * 8;
        *(float4*)dst = make_float4(v[0], v[1], v[2], v[3]);
        *(float4*)(dst + 4) = make_float4(v[4], v[5], v[6], v[7]);
    }
}

// ---------------- K3a: Who = hcat @ W_out  (M=4096, K=512, N=16) ----------------
__global__ void __launch_bounds__(256) k_gemm2(const float* __restrict__ Wout) {
    __shared__ float hs[64][65];
    __shared__ float4 wos[64][4];
    int r0 = blockIdx.x * 64;
    int t = threadIdx.x;
    int row = t >> 2, cg = t & 3;
    float4 acc = make_float4(0.f, 0.f, 0.f, 0.f);
    for (int k0 = 0; k0 < F; k0 += 64) {
        for (int idx = t; idx < 64 * 64; idx += 256) {
            int r = idx >> 6, k = idx & 63;
            hs[r][k] = g_hcat[(r0 + r) * F + k0 + k];
        }
        for (int idx = t; idx < 64 * 16; idx += 256) {
            int k = idx >> 4, c = idx & 15;
            ((float*)wos)[k * 16 + c] = Wout[(k0 + k) * C + c];
        }
        __syncthreads();
#pragma unroll
        for (int k = 0; k < 64; ++k) {
            float hv = hs[row][k];
            float4 wv = wos[k][cg];
            acc.x += hv * wv.x; acc.y += hv * wv.y;
            acc.z += hv * wv.z; acc.w += hv * wv.w;
        }
        __syncthreads();
    }
    float* dst = g_Who + (r0 + row) * C + cg * 4;
    dst[0] = acc.x; dst[1] = acc.y; dst[2] = acc.z; dst[3] = acc.w;
}

// ---------------- K3b: per-node scores + exponentials (layer 2) ----------------
__global__ void k_scores2(const float* __restrict__ aout) {
    int gw = (blockIdx.x * blockDim.x + threadIdx.x) >> 5;  // node id
    int lane = threadIdx.x & 31;
    float v1 = 0.f, v2 = 0.f;
    if (lane < C) {
        float w = g_Who[gw * C + lane];
        v1 = w * aout[lane];
        v2 = w * aout[C + lane];
    }
#pragma unroll
    for (int off = 8; off; off >>= 1) {
        v1 += __shfl_down_sync(0xffffffffu, v1, off);
        v2 += __shfl_down_sync(0xffffffffu, v2, off);
    }
    if (lane == 0) {
        g2_E1pn[gw] = make_float2(expf(v1), expf(0.2f * v1));
        g2_E2pn[gw] = make_float2(expf(v2), expf(0.2f * v2));
    }
}

// ---------------- K4: layer-2 aggregate + ELU + log_softmax ----------------
// grid N/32 = 128, 128 threads. Same phased structure, 32 rows per block.
__global__ void __launch_bounds__(128, 4) k_agg2(float* __restrict__ out) {
    __shared__ float2 s_who[32 * 16];  // whoi[jp][c] = (Who[2jp][c], Who[2jp+1][c])
    __shared__ float  s_pt[32 * 70];
    __shared__ float  s_dp[32][4];
    __shared__ float  s_v[32][16];
    int r0 = blockIdx.x * 32;
    int t = threadIdx.x;
    int ty = t >> 3, tx = t & 7;      // phase-2: 2 rows, 2 cols
    int prow = t >> 2, q = t & 3;     // phase-1: row, quarter (16 j each)

    ull e1u = f2u(g2_E1pn[r0 + prow]);
    float denl = 0.f;

    ull acc[2][2];
    acc[0][0] = acc[0][1] = acc[1][0] = acc[1][1] = 0ull;

    for (int j0 = 0; j0 < N; j0 += 64) {
        // phase 0: Who tile, j-interleaved (no pad needed: 16 f2 per row)
        {
            int jp = t >> 2, c4 = t & 3;
            const float* wb = g_Who + (j0 + 2 * jp) * C + c4 * 4;
            float4 a = *(const float4*)wb;
            float4 b = *(const float4*)(wb + C);
            float2* d = &s_who[jp * 16 + c4 * 4];
            d[0] = make_float2(a.x, b.x);
            d[1] = make_float2(a.y, b.y);
            d[2] = make_float2(a.z, b.z);
            d[3] = make_float2(a.w, b.w);
        }
        // phase 1: weights
        {
            unsigned m = g_mask[(r0 + prow) * NW + (j0 >> 5) + (q >> 1)];
            int bit0 = (q & 1) * 16;
            const float2* e2p = &g2_E2pn[j0 + q * 16];
#pragma unroll
            for (int jj = 0; jj < 16; jj += 2) {
                float2 fa = u2f(mul2(e1u, f2u(e2p[jj])));
                float2 fb = u2f(mul2(e1u, f2u(e2p[jj + 1])));
                float w0 = fmaxf(fa.x, fa.y);
                float w1 = fmaxf(fb.x, fb.y);
                w0 = ((m >> (bit0 + jj)) & 1u) ? w0 : 0.f;
                w1 = ((m >> (bit0 + jj + 1)) & 1u) ? w1 : 0.f;
                denl += w0 + w1;
                *(float2*)&s_pt[prow * 70 + q * 16 + jj] = make_float2(w0, w1);
            }
        }
        __syncthreads();
        // phase 2
#pragma unroll 4
        for (int jp = 0; jp < 32; ++jp) {
            ull p0 = *(const ull*)&s_pt[(ty * 2 + 0) * 70 + 2 * jp];
            ull p1 = *(const ull*)&s_pt[(ty * 2 + 1) * 70 + 2 * jp];
            const ull* wv = (const ull*)&s_who[jp * 16 + tx * 2];
            ull wx = wv[0], wy = wv[1];
            acc[0][0] = fma2(p0, wx, acc[0][0]);
            acc[0][1] = fma2(p0, wy, acc[0][1]);
            acc[1][0] = fma2(p1, wx, acc[1][0]);
            acc[1][1] = fma2(p1, wy, acc[1][1]);
        }
        __syncthreads();
    }
    s_dp[prow][q] = denl;
    __syncthreads();
#pragma unroll
    for (int i = 0; i < 2; ++i) {
        int r = ty * 2 + i;
        float inv = 1.f / (s_dp[r][0] + s_dp[r][1] + s_dp[r][2] + s_dp[r][3]);
#pragma unroll
        for (int c = 0; c < 2; ++c) {
            float2 f = u2f(acc[i][c]);
            float s = (f.x + f.y) * inv;
            s_v[r][tx * 2 + c] = (s > 0.f) ? s : (expf(s) - 1.f);
        }
    }
    __syncthreads();
    if (t < 32) {
        float v[16];
        float mx = -1e30f;
#pragma unroll
        for (int c = 0; c < C; ++c) { v[c] = s_v[t][c]; mx = fmaxf(mx, v[c]); }
        float s = 0.f;
#pragma unroll
        for (int c = 0; c < C; ++c) s += expf(v[c] - mx);
        float lse = mx + logf(s);
#pragma unroll
        for (int c = 0; c < C; ++c) out[(r0 + t) * C + c] = v[c] - lse;
    }
}

// ---------------- launch ----------------
extern "C" void kernel_launch(void* const* d_in, const int* in_sizes, int n_in,
                              void* d_out, int out_size) {
    const float* x    = (const float*)d_in[0];
    const int*   adj  = (const int*)d_in[1];
    const float* W    = (const float*)d_in[2];
    const float* a    = (const float*)d_in[3];
    const float* Wout = (const float*)d_in[4];
    const float* aout = (const float*)d_in[5];
    float* out = (float*)d_out;

    k_pack<<<N * NW / 8, 256>>>(adj);
    k_gemm1<<<dim3(N / 64, H), 128>>>(x, W);
    k_scores1<<<H * N / 8, 256>>>(a);
    k_agg1<<<dim3(N / 64, H), 128>>>();
    k_gemm2<<<N / 64, 256>>>(Wout);
    k_scores2<<<N / 8, 256>>>(aout);
    k_agg2<<<N / 32, 128>>>(out);
}

// round 9
// speedup vs baseline: 3.9294x; 3.9294x over previous
#include <cuda_runtime.h>
#include <cuda_bf16.h>
#include <math.h>
#include <cstdint>

#define N 4096
#define F 512
#define O 64
#define H 8
#define C 16
#define NW 128  // mask words per row (N/32)

// -------- scratch (static device globals; no allocation) --------
__device__ unsigned g_mask[N * NW];            // 2 MB bit-packed adjacency
__device__ float g_Wh[H * N * O];              // 8 MB fp32 (for scores)
__device__ __nv_bfloat16 g_Whb[H * N * O];     // 4 MB bf16 [h][node][col]
__device__ float2 g_E1pn[H * N];               // (exp(v1), exp(0.2 v1))
__device__ float2 g_E2pn[H * N];
__device__ float g_hcat[N * F];                // 8 MB  (F == H*O)
__device__ float g_Who[N * C];
__device__ __nv_bfloat16 g_Whob[N * C];
__device__ float2 g2_E1pn[N], g2_E2pn[N];

// -------- helpers --------
__device__ __forceinline__ uint32_t smem_u32(const void* p) {
    uint32_t a;
    asm("{ .reg .u64 t; cvta.to.shared.u64 t, %1; cvt.u32.u64 %0, t; }" : "=r"(a) : "l"(p));
    return a;
}
__device__ __forceinline__ void ldsm_x4(uint32_t& r0, uint32_t& r1, uint32_t& r2,
                                        uint32_t& r3, uint32_t addr) {
    asm volatile("ldmatrix.sync.aligned.m8n8.x4.shared.b16 {%0,%1,%2,%3}, [%4];"
                 : "=r"(r0), "=r"(r1), "=r"(r2), "=r"(r3) : "r"(addr));
}
__device__ __forceinline__ void ldsm_x4t(uint32_t& r0, uint32_t& r1, uint32_t& r2,
                                         uint32_t& r3, uint32_t addr) {
    asm volatile("ldmatrix.sync.aligned.m8n8.x4.trans.shared.b16 {%0,%1,%2,%3}, [%4];"
                 : "=r"(r0), "=r"(r1), "=r"(r2), "=r"(r3) : "r"(addr));
}
__device__ __forceinline__ void mma_bf16(float* c, uint32_t a0, uint32_t a1, uint32_t a2,
                                         uint32_t a3, uint32_t b0, uint32_t b1) {
    asm volatile(
        "mma.sync.aligned.m16n8k16.row.col.f32.bf16.bf16.f32 "
        "{%0,%1,%2,%3}, {%4,%5,%6,%7}, {%8,%9}, {%0,%1,%2,%3};"
        : "+f"(c[0]), "+f"(c[1]), "+f"(c[2]), "+f"(c[3])
        : "r"(a0), "r"(a1), "r"(a2), "r"(a3), "r"(b0), "r"(b1));
}
__device__ __forceinline__ uint32_t b2u(__nv_bfloat162 v) {
    return *reinterpret_cast<uint32_t*>(&v);
}
__device__ __forceinline__ float elu(float s) { return (s > 0.f) ? s : (expf(s) - 1.f); }

// ---------------- K0: pack adjacency to bits ----------------
__global__ void k_pack(const int* __restrict__ adj) {
    int gt = blockIdx.x * blockDim.x + threadIdx.x;
    int w = gt >> 5, lane = gt & 31;
    int i = w >> 7, jw = w & (NW - 1);
    int v = adj[i * N + jw * 32 + lane];
    unsigned m = __ballot_sync(0xffffffffu, v > 0);
    if (lane == 0) g_mask[w] = m;
}

// ---------------- K1: Wh[h] = x @ W[h]; emits fp32 + bf16 copies ----------------
__global__ void __launch_bounds__(256) k_gemm1(const float* __restrict__ x,
                                               const float* __restrict__ W) {
    __shared__ float xs[64][33];
    __shared__ float4 ws[32][16];
    int h = blockIdx.y;
    int r0 = blockIdx.x * 64;
    int t = threadIdx.x;
    int ty = t >> 4, tx = t & 15;
    float4 acc[4];
#pragma unroll
    for (int r = 0; r < 4; ++r) acc[r] = make_float4(0.f, 0.f, 0.f, 0.f);

    for (int k0 = 0; k0 < F; k0 += 32) {
        for (int idx = t; idx < 64 * 32; idx += 256) {
            int r = idx >> 5, k = idx & 31;
            xs[r][k] = x[(r0 + r) * F + k0 + k];
        }
        for (int idx = t; idx < 32 * 64; idx += 256) {
            int k = idx >> 6, o = idx & 63;
            ((float*)ws)[k * 64 + o] = W[h * F * O + (k0 + k) * O + o];
        }
        __syncthreads();
#pragma unroll
        for (int k = 0; k < 32; ++k) {
            float4 wv = ws[k][tx];
#pragma unroll
            for (int r = 0; r < 4; ++r) {
                float xa = xs[ty * 4 + r][k];
                acc[r].x += xa * wv.x; acc[r].y += xa * wv.y;
                acc[r].z += xa * wv.z; acc[r].w += xa * wv.w;
            }
        }
        __syncthreads();
    }
#pragma unroll
    for (int r = 0; r < 4; ++r) {
        int row = r0 + ty * 4 + r;
        float* dst = g_Wh + (h * N + row) * O + tx * 4;
        dst[0] = acc[r].x; dst[1] = acc[r].y; dst[2] = acc[r].z; dst[3] = acc[r].w;
        uint2 pk;
        pk.x = b2u(__floats2bfloat162_rn(acc[r].x, acc[r].y));
        pk.y = b2u(__floats2bfloat162_rn(acc[r].z, acc[r].w));
        *(uint2*)&g_Whb[(h * N + row) * O + tx * 4] = pk;
    }
}

// ---------------- K1b: per-node scores + factored exponentials (layer 1) ----------------
__global__ void k_scores1(const float* __restrict__ a) {
    int gw = (blockIdx.x * blockDim.x + threadIdx.x) >> 5;  // gw = h*N + n
    int lane = threadIdx.x & 31;
    int h = gw >> 12;
    const float* wh = g_Wh + gw * O;
    const float* ah = a + h * 2 * O;
    float w0 = wh[lane], w1 = wh[lane + 32];
    float v1 = w0 * ah[lane] + w1 * ah[lane + 32];
    float v2 = w0 * ah[O + lane] + w1 * ah[O + lane + 32];
#pragma unroll
    for (int off = 16; off; off >>= 1) {
        v1 += __shfl_down_sync(0xffffffffu, v1, off);
        v2 += __shfl_down_sync(0xffffffffu, v2, off);
    }
    if (lane == 0) {
        g_E1pn[gw] = make_float2(expf(v1), expf(0.2f * v1));
        g_E2pn[gw] = make_float2(expf(v2), expf(0.2f * v2));
    }
}

// ---------------- K2: layer-1 aggregate via mma.sync bf16 ----------------
// grid (N/64, H), 128 threads (4 warps x 16 rows). j-tiles of 64.
__global__ void __launch_bounds__(128, 4) k_agg1_mma() {
    __shared__ __align__(16) uint16_t P_s[64 * 136];     // P tile, stride 136 bf16
    __shared__ __align__(16) uint16_t Whb_s[64 * 72];    // Wh tile [j][c], stride 72
    __shared__ uint2 e2s[32];                            // {e2p pair, e2n pair}
    __shared__ uint2 lut_s[16];                          // 4 bits -> 2 pair masks

    int t = threadIdx.x;
    int w = t >> 5, lane = t & 31;
    int h = blockIdx.y, hN = h * N;
    int r0 = blockIdx.x * 64;

    if (t < 16) {
        uint32_t lo = ((t & 1) ? 0xFFFFu : 0u) | ((t & 2) ? 0xFFFF0000u : 0u);
        uint32_t hi = ((t & 4) ? 0xFFFFu : 0u) | ((t & 8) ? 0xFFFF0000u : 0u);
        lut_s[t] = make_uint2(lo, hi);
    }

    int prow = t >> 1;                  // P-gen row (0..63)
    float2 e1 = g_E1pn[hN + r0 + prow];
    uint32_t e1p2 = b2u(__float2bfloat162_rn(e1.x));
    uint32_t e1n2 = b2u(__float2bfloat162_rn(e1.y));

    float c[9][4];
#pragma unroll
    for (int i = 0; i < 9; ++i)
#pragma unroll
        for (int q = 0; q < 4; ++q) c[i][q] = 0.f;
    const uint32_t b_ones = 0x3F803F80u;

    // precomputed ldmatrix lane addressing pieces
    int mrow = lane >> 3;                       // matrix id 0..3
    int arow = w * 16 + (mrow & 1) * 8 + (lane & 7);
    int koff = (mrow >> 1) * 8;
    int brow8 = (mrow & 1) * 8 + (lane & 7);

    for (int tile = 0; tile < 64; ++tile) {
        int j0 = tile * 64;
        __syncthreads();
        // stage Wh tile (bf16): 64 rows x 8 chunks of 8 bf16
#pragma unroll
        for (int it = 0; it < 4; ++it) {
            int u = t + it * 128;             // 0..511
            int j = u >> 3, c8 = (u & 7) * 8;
            uint4 v = *(const uint4*)&g_Whb[(size_t)(hN + j0 + j) * O + c8];
            *(uint4*)&Whb_s[j * 72 + c8] = v;
        }
        if (t < 32) {
            float4 e = *(const float4*)&g_E2pn[hN + j0 + 2 * t];
            uint2 pk;
            pk.x = b2u(__floats2bfloat162_rn(e.x, e.z));   // e2p (j, j+1)
            pk.y = b2u(__floats2bfloat162_rn(e.y, e.w));   // e2n (j, j+1)
            e2s[t] = pk;
        }
        __syncthreads();
        // P-gen: each thread: row prow, 32 j's
        {
            int jh = (t & 1) * 32;
            unsigned m = g_mask[(r0 + prow) * NW + (j0 >> 5) + (t & 1)];
            const __nv_bfloat162 E1P = *reinterpret_cast<__nv_bfloat162*>(&e1p2);
            const __nv_bfloat162 E1N = *reinterpret_cast<__nv_bfloat162*>(&e1n2);
#pragma unroll
            for (int q = 0; q < 8; ++q) {
                uint2 msk = lut_s[(m >> (q * 4)) & 0xF];
                uint2 ea = e2s[(jh >> 1) + q * 2];
                uint2 eb = e2s[(jh >> 1) + q * 2 + 1];
                __nv_bfloat162 pa = __hmul2(E1P, *reinterpret_cast<__nv_bfloat162*>(&ea.x));
                __nv_bfloat162 na = __hmul2(E1N, *reinterpret_cast<__nv_bfloat162*>(&ea.y));
                __nv_bfloat162 pb = __hmul2(E1P, *reinterpret_cast<__nv_bfloat162*>(&eb.x));
                __nv_bfloat162 nb = __hmul2(E1N, *reinterpret_cast<__nv_bfloat162*>(&eb.y));
                __nv_bfloat162 ma = __hmax2(pa, na);
                __nv_bfloat162 mb = __hmax2(pb, nb);
                uint32_t w0 = b2u(ma) & msk.x;
                uint32_t w1 = b2u(mb) & msk.y;
                *(uint2*)&P_s[prow * 136 + jh + q * 4] = make_uint2(w0, w1);
            }
        }
        __syncthreads();
        // MMA phase
#pragma unroll
        for (int ks = 0; ks < 4; ++ks) {
            uint32_t a0, a1, a2, a3;
            ldsm_x4(a0, a1, a2, a3,
                    smem_u32(&P_s[arow * 136 + ks * 16 + koff]));
#pragma unroll
            for (int nb = 0; nb < 4; ++nb) {
                uint32_t b0, b1, b2, b3;
                ldsm_x4t(b0, b1, b2, b3,
                         smem_u32(&Whb_s[(ks * 16 + brow8) * 72 + nb * 16 + koff]));
                mma_bf16(c[nb * 2],     a0, a1, a2, a3, b0, b1);
                mma_bf16(c[nb * 2 + 1], a0, a1, a2, a3, b2, b3);
            }
            mma_bf16(c[8], a0, a1, a2, a3, b_ones, b_ones);
        }
    }

    // epilogue: divide by den (c[8]), ELU, store fp32
    {
        int rA = r0 + w * 16 + (lane >> 2);
        int rB = rA + 8;
        float invA = 1.f / c[8][0];
        float invB = 1.f / c[8][2];
        int cbase = h * O + (lane & 3) * 2;
#pragma unroll
        for (int nt = 0; nt < 8; ++nt) {
            float2 vA = make_float2(elu(c[nt][0] * invA), elu(c[nt][1] * invA));
            float2 vB = make_float2(elu(c[nt][2] * invB), elu(c[nt][3] * invB));
            *(float2*)&g_hcat[(size_t)rA * F + cbase + nt * 8] = vA;
            *(float2*)&g_hcat[(size_t)rB * F + cbase + nt * 8] = vB;
        }
    }
}

// ---------------- K3a: Who = hcat @ W_out; emits fp32 + bf16 ----------------
__global__ void __launch_bounds__(256) k_gemm2(const float* __restrict__ Wout) {
    __shared__ float hs[64][65];
    __shared__ float4 wos[64][4];
    int r0 = blockIdx.x * 64;
    int t = threadIdx.x;
    int row = t >> 2, cg = t & 3;
    float4 acc = make_float4(0.f, 0.f, 0.f, 0.f);
    for (int k0 = 0; k0 < F; k0 += 64) {
        for (int idx = t; idx < 64 * 64; idx += 256) {
            int r = idx >> 6, k = idx & 63;
            hs[r][k] = g_hcat[(r0 + r) * F + k0 + k];
        }
        for (int idx = t; idx < 64 * 16; idx += 256) {
            int k = idx >> 4, c = idx & 15;
            ((float*)wos)[k * 16 + c] = Wout[(k0 + k) * C + c];
        }
        __syncthreads();
#pragma unroll
        for (int k = 0; k < 64; ++k) {
            float hv = hs[row][k];
            float4 wv = wos[k][cg];
            acc.x += hv * wv.x; acc.y += hv * wv.y;
            acc.z += hv * wv.z; acc.w += hv * wv.w;
        }
        __syncthreads();
    }
    float* dst = g_Who + (r0 + row) * C + cg * 4;
    dst[0] = acc.x; dst[1] = acc.y; dst[2] = acc.z; dst[3] = acc.w;
    uint2 pk;
    pk.x = b2u(__floats2bfloat162_rn(acc.x, acc.y));
    pk.y = b2u(__floats2bfloat162_rn(acc.z, acc.w));
    *(uint2*)&g_Whob[(r0 + row) * C + cg * 4] = pk;
}

// ---------------- K3b: per-node scores + exponentials (layer 2) ----------------
__global__ void k_scores2(const float* __restrict__ aout) {
    int gw = (blockIdx.x * blockDim.x + threadIdx.x) >> 5;  // node id
    int lane = threadIdx.x & 31;
    float v1 = 0.f, v2 = 0.f;
    if (lane < C) {
        float w = g_Who[gw * C + lane];
        v1 = w * aout[lane];
        v2 = w * aout[C + lane];
    }
#pragma unroll
    for (int off = 8; off; off >>= 1) {
        v1 += __shfl_down_sync(0xffffffffu, v1, off);
        v2 += __shfl_down_sync(0xffffffffu, v2, off);
    }
    if (lane == 0) {
        g2_E1pn[gw] = make_float2(expf(v1), expf(0.2f * v1));
        g2_E2pn[gw] = make_float2(expf(v2), expf(0.2f * v2));
    }
}

// ---------------- K4: layer-2 aggregate via mma.sync + log_softmax ----------------
// grid N/64 = 64 blocks, 128 threads.
__global__ void __launch_bounds__(128, 4) k_agg2_mma(float* __restrict__ out) {
    __shared__ __align__(16) uint16_t P_s[64 * 136];
    __shared__ __align__(16) uint16_t Who_s[64 * 24];    // [j][c] stride 24
    __shared__ uint2 e2s[32];
    __shared__ uint2 lut_s[16];

    int t = threadIdx.x;
    int w = t >> 5, lane = t & 31;
    int r0 = blockIdx.x * 64;

    if (t < 16) {
        uint32_t lo = ((t & 1) ? 0xFFFFu : 0u) | ((t & 2) ? 0xFFFF0000u : 0u);
        uint32_t hi = ((t & 4) ? 0xFFFFu : 0u) | ((t & 8) ? 0xFFFF0000u : 0u);
        lut_s[t] = make_uint2(lo, hi);
    }

    int prow = t >> 1;
    float2 e1 = g2_E1pn[r0 + prow];
    uint32_t e1p2 = b2u(__float2bfloat162_rn(e1.x));
    uint32_t e1n2 = b2u(__float2bfloat162_rn(e1.y));

    float c[3][4];
#pragma unroll
    for (int i = 0; i < 3; ++i)
#pragma unroll
        for (int q = 0; q < 4; ++q) c[i][q] = 0.f;
    const uint32_t b_ones = 0x3F803F80u;

    int mrow = lane >> 3;
    int arow = w * 16 + (mrow & 1) * 8 + (lane & 7);
    int koff = (mrow >> 1) * 8;
    int brow8 = (mrow & 1) * 8 + (lane & 7);

    for (int tile = 0; tile < 64; ++tile) {
        int j0 = tile * 64;
        __syncthreads();
        {   // stage Who tile: 64 rows x 2 chunks of 8 bf16
            int j = t >> 1, half = t & 1;
            uint4 v = *(const uint4*)&g_Whob[(j0 + j) * C + half * 8];
            *(uint4*)&Who_s[j * 24 + half * 8] = v;
        }
        if (t < 32) {
            float4 e = *(const float4*)&g2_E2pn[j0 + 2 * t];
            uint2 pk;
            pk.x = b2u(__floats2bfloat162_rn(e.x, e.z));
            pk.y = b2u(__floats2bfloat162_rn(e.y, e.w));
            e2s[t] = pk;
        }
        __syncthreads();
        {   // P-gen
            int jh = (t & 1) * 32;
            unsigned m = g_mask[(r0 + prow) * NW + (j0 >> 5) + (t & 1)];
            const __nv_bfloat162 E1P = *reinterpret_cast<__nv_bfloat162*>(&e1p2);
            const __nv_bfloat162 E1N = *reinterpret_cast<__nv_bfloat162*>(&e1n2);
#pragma unroll
            for (int q = 0; q < 8; ++q) {
                uint2 msk = lut_s[(m >> (q * 4)) & 0xF];
                uint2 ea = e2s[(jh >> 1) + q * 2];
                uint2 eb = e2s[(jh >> 1) + q * 2 + 1];
                __nv_bfloat162 pa = __hmul2(E1P, *reinterpret_cast<__nv_bfloat162*>(&ea.x));
                __nv_bfloat162 na = __hmul2(E1N, *reinterpret_cast<__nv_bfloat162*>(&ea.y));
                __nv_bfloat162 pb = __hmul2(E1P, *reinterpret_cast<__nv_bfloat162*>(&eb.x));
                __nv_bfloat162 nb = __hmul2(E1N, *reinterpret_cast<__nv_bfloat162*>(&eb.y));
                __nv_bfloat162 ma = __hmax2(pa, na);
                __nv_bfloat162 mb = __hmax2(pb, nb);
                uint32_t w0 = b2u(ma) & msk.x;
                uint32_t w1 = b2u(mb) & msk.y;
                *(uint2*)&P_s[prow * 136 + jh + q * 4] = make_uint2(w0, w1);
            }
        }
        __syncthreads();
        // MMA
#pragma unroll
        for (int ks = 0; ks < 4; ++ks) {
            uint32_t a0, a1, a2, a3;
            ldsm_x4(a0, a1, a2, a3,
                    smem_u32(&P_s[arow * 136 + ks * 16 + koff]));
            uint32_t b0, b1, b2, b3;
            ldsm_x4t(b0, b1, b2, b3,
                     smem_u32(&Who_s[(ks * 16 + brow8) * 24 + koff]));
            mma_bf16(c[0], a0, a1, a2, a3, b0, b1);
            mma_bf16(c[1], a0, a1, a2, a3, b2, b3);
            mma_bf16(c[2], a0, a1, a2, a3, b_ones, b_ones);
        }
    }

    // epilogue: divide, ELU, log_softmax over 16 cols (4 lanes per row)
    {
        int rA = r0 + w * 16 + (lane >> 2);
        int rB = rA + 8;
        float invA = 1.f / c[2][0];
        float invB = 1.f / c[2][2];
        float vA[4] = {elu(c[0][0] * invA), elu(c[0][1] * invA),
                       elu(c[1][0] * invA), elu(c[1][1] * invA)};
        float vB[4] = {elu(c[0][2] * invB), elu(c[0][3] * invB),
                       elu(c[1][2] * invB), elu(c[1][3] * invB)};
        float mxA = fmaxf(fmaxf(vA[0], vA[1]), fmaxf(vA[2], vA[3]));
        float mxB = fmaxf(fmaxf(vB[0], vB[1]), fmaxf(vB[2], vB[3]));
        mxA = fmaxf(mxA, __shfl_xor_sync(0xffffffffu, mxA, 1));
        mxA = fmaxf(mxA, __shfl_xor_sync(0xffffffffu, mxA, 2));
        mxB = fmaxf(mxB, __shfl_xor_sync(0xffffffffu, mxB, 1));
        mxB = fmaxf(mxB, __shfl_xor_sync(0xffffffffu, mxB, 2));
        float sA = expf(vA[0] - mxA) + expf(vA[1] - mxA) + expf(vA[2] - mxA) + expf(vA[3] - mxA);
        float sB = expf(vB[0] - mxB) + expf(vB[1] - mxB) + expf(vB[2] - mxB) + expf(vB[3] - mxB);
        sA += __shfl_xor_sync(0xffffffffu, sA, 1);
        sA += __shfl_xor_sync(0xffffffffu, sA, 2);
        sB += __shfl_xor_sync(0xffffffffu, sB, 1);
        sB += __shfl_xor_sync(0xffffffffu, sB, 2);
        float lseA = mxA + logf(sA);
        float lseB = mxB + logf(sB);
        int c0 = (lane & 3) * 2;
        *(float2*)&out[rA * C + c0]     = make_float2(vA[0] - lseA, vA[1] - lseA);
        *(float2*)&out[rA * C + 8 + c0] = make_float2(vA[2] - lseA, vA[3] - lseA);
        *(float2*)&out[rB * C + c0]     = make_float2(vB[0] - lseB, vB[1] - lseB);
        *(float2*)&out[rB * C + 8 + c0] = make_float2(vB[2] - lseB, vB[3] - lseB);
    }
}

// ---------------- launch ----------------
extern "C" void kernel_launch(void* const* d_in, const int* in_sizes, int n_in,
                              void* d_out, int out_size) {
    const float* x    = (const float*)d_in[0];
    const int*   adj  = (const int*)d_in[1];
    const float* W    = (const float*)d_in[2];
    const float* a    = (const float*)d_in[3];
    const float* Wout = (const float*)d_in[4];
    const float* aout = (const float*)d_in[5];
    float* out = (float*)d_out;

    k_pack<<<N * NW / 8, 256>>>(adj);
    k_gemm1<<<dim3(N / 64, H), 256>>>(x, W);
    k_scores1<<<H * N / 8, 256>>>(a);
    k_agg1_mma<<<dim3(N / 64, H), 128>>>();
    k_gemm2<<<N / 64, 256>>>(Wout);
    k_scores2<<<N / 8, 256>>>(aout);
    k_agg2_mma<<<N / 64, 128>>>(out);
}

// round 10
// speedup vs baseline: 3.9454x; 1.0041x over previous
#include <cuda_runtime.h>
#include <cuda_bf16.h>
#include <math.h>
#include <cstdint>

#define N 4096
#define F 512
#define O 64
#define H 8
#define C 16
#define NW 128  // mask words per row (N/32)

// -------- scratch (static device globals; no allocation) --------
__device__ unsigned g_mask[N * NW];            // 2 MB bit-packed adjacency
__device__ __nv_bfloat16 g_Whb[H * N * O];     // 4 MB bf16 [h][node][col]
__device__ float g_av[2 * H * F];              // W[h]@a1 / W[h]@a2 vectors
__device__ float2 g_E1pn[H * N];               // (exp(v1), exp(0.2 v1))
__device__ float2 g_E2pn[H * N];
__device__ __nv_bfloat16 g_hcatb[N * F];       // 4 MB bf16 (F == H*O)
__device__ float g_Who[N * C];
__device__ __nv_bfloat16 g_Whob[N * C];
__device__ float2 g2_E1pn[N], g2_E2pn[N];

// -------- helpers --------
__device__ __forceinline__ uint32_t smem_u32(const void* p) {
    uint32_t a;
    asm("{ .reg .u64 t; cvta.to.shared.u64 t, %1; cvt.u32.u64 %0, t; }" : "=r"(a) : "l"(p));
    return a;
}
__device__ __forceinline__ void ldsm_x4t(uint32_t& r0, uint32_t& r1, uint32_t& r2,
                                         uint32_t& r3, uint32_t addr) {
    asm volatile("ldmatrix.sync.aligned.m8n8.x4.trans.shared.b16 {%0,%1,%2,%3}, [%4];"
                 : "=r"(r0), "=r"(r1), "=r"(r2), "=r"(r3) : "r"(addr));
}
__device__ __forceinline__ void ldsm_x4(uint32_t& r0, uint32_t& r1, uint32_t& r2,
                                        uint32_t& r3, uint32_t addr) {
    asm volatile("ldmatrix.sync.aligned.m8n8.x4.shared.b16 {%0,%1,%2,%3}, [%4];"
                 : "=r"(r0), "=r"(r1), "=r"(r2), "=r"(r3) : "r"(addr));
}
__device__ __forceinline__ void mma_bf16(float* c, uint32_t a0, uint32_t a1, uint32_t a2,
                                         uint32_t a3, uint32_t b0, uint32_t b1) {
    asm volatile(
        "mma.sync.aligned.m16n8k16.row.col.f32.bf16.bf16.f32 "
        "{%0,%1,%2,%3}, {%4,%5,%6,%7}, {%8,%9}, {%0,%1,%2,%3};"
        : "+f"(c[0]), "+f"(c[1]), "+f"(c[2]), "+f"(c[3])
        : "r"(a0), "r"(a1), "r"(a2), "r"(a3), "r"(b0), "r"(b1));
}
__device__ __forceinline__ uint32_t b2u(__nv_bfloat162 v) {
    return *reinterpret_cast<uint32_t*>(&v);
}
__device__ __forceinline__ __nv_bfloat162 u2b(uint32_t v) {
    return *reinterpret_cast<__nv_bfloat162*>(&v);
}
__device__ __forceinline__ float elu(float s) { return (s > 0.f) ? s : (expf(s) - 1.f); }

// pair-mask for adjacency bits (bit, bit+1) of mword -> low/high 16-bit lanes
__device__ __forceinline__ uint32_t pairmask(uint32_t mword, int bit) {
    uint32_t m2 = (mword >> bit) & 3u;
    return ((m2 & 1u) ? 0xFFFFu : 0u) | ((m2 & 2u) ? 0xFFFF0000u : 0u);
}
// weight pair: max(e1p*e2p, e1n*e2n) masked
__device__ __forceinline__ uint32_t wpair(uint32_t E1P, uint32_t E1N, uint2 e2, uint32_t msk) {
    __nv_bfloat162 p = __hmul2(u2b(E1P), u2b(e2.x));
    __nv_bfloat162 n = __hmul2(u2b(E1N), u2b(e2.y));
    return b2u(__hmax2(p, n)) & msk;
}

// ---------------- K0: pack adjacency to bits ----------------
__global__ void k_pack(const int* __restrict__ adj) {
    int gt = blockIdx.x * blockDim.x + threadIdx.x;
    int w = gt >> 5, lane = gt & 31;
    int i = w >> 7, jw = w & (NW - 1);
    int v = adj[i * N + jw * 32 + lane];
    unsigned m = __ballot_sync(0xffffffffu, v > 0);
    if (lane == 0) g_mask[w] = m;
}

// ---------------- K0b: av[h][s][:] = W[h] @ a_s[h]  (fp32 exact) ----------------
__global__ void k_prevec(const float* __restrict__ W, const float* __restrict__ a) {
    int u = blockIdx.x * blockDim.x + threadIdx.x;   // 0..8191
    int h = u >> 10, s = (u >> 9) & 1, f = u & 511;
    const float* wp = W + (h * F + f) * O;
    const float* ap = a + h * 2 * O + s * O;
    float v = 0.f;
#pragma unroll
    for (int o = 0; o < O; ++o) v += wp[o] * ap[o];
    g_av[(h * 2 + s) * F + f] = v;
}

// ---------------- K1: Whb[h] = bf16(x @ W[h]) via mma.sync ----------------
// grid (N/64, H), 128 threads.
__global__ void __launch_bounds__(128) k_gemm1_mma(const float* __restrict__ x,
                                                   const float* __restrict__ W) {
    __shared__ __align__(16) uint16_t Xs[64 * 72];   // [row][k] bf16
    __shared__ __align__(16) uint16_t Ws[64 * 72];   // [k][o] bf16
    int t = threadIdx.x;
    int w = t >> 5, lane = t & 31;
    int h = blockIdx.y;
    int r0 = blockIdx.x * 64;

    float c[8][4];
#pragma unroll
    for (int i = 0; i < 8; ++i)
#pragma unroll
        for (int q = 0; q < 4; ++q) c[i][q] = 0.f;

    int mrow = lane >> 3;
    int arow = w * 16 + (mrow & 1) * 8 + (lane & 7);
    int koff = (mrow >> 1) * 8;
    int brow8 = (mrow & 1) * 8 + (lane & 7);

    for (int kc = 0; kc < 8; ++kc) {
        int k0 = kc * 64;
        __syncthreads();
        // stage X: 64 rows x 64 k (fp32 -> bf16)
#pragma unroll
        for (int it = 0; it < 8; ++it) {
            int u = t + it * 128;                 // 0..1023 float4 chunks
            int r = u >> 4, kq = (u & 15) * 4;
            float4 v = *(const float4*)&x[(size_t)(r0 + r) * F + k0 + kq];
            uint2 pk;
            pk.x = b2u(__floats2bfloat162_rn(v.x, v.y));
            pk.y = b2u(__floats2bfloat162_rn(v.z, v.w));
            *(uint2*)&Xs[r * 72 + kq] = pk;
        }
        // stage W: 64 k x 64 o
#pragma unroll
        for (int it = 0; it < 8; ++it) {
            int u = t + it * 128;
            int k = u >> 4, oq = (u & 15) * 4;
            float4 v = *(const float4*)&W[((size_t)h * F + k0 + k) * O + oq];
            uint2 pk;
            pk.x = b2u(__floats2bfloat162_rn(v.x, v.y));
            pk.y = b2u(__floats2bfloat162_rn(v.z, v.w));
            *(uint2*)&Ws[k * 72 + oq] = pk;
        }
        __syncthreads();
#pragma unroll
        for (int ks = 0; ks < 4; ++ks) {
            uint32_t a0, a1, a2, a3;
            ldsm_x4(a0, a1, a2, a3, smem_u32(&Xs[arow * 72 + ks * 16 + koff]));
#pragma unroll
            for (int nb = 0; nb < 4; ++nb) {
                uint32_t b0, b1, b2, b3;
                ldsm_x4t(b0, b1, b2, b3,
                         smem_u32(&Ws[(ks * 16 + brow8) * 72 + nb * 16 + koff]));
                mma_bf16(c[nb * 2],     a0, a1, a2, a3, b0, b1);
                mma_bf16(c[nb * 2 + 1], a0, a1, a2, a3, b2, b3);
            }
        }
    }
    // epilogue: bf16 store
    {
        int rA = r0 + w * 16 + (lane >> 2);
        int rB = rA + 8;
        int c0 = (lane & 3) * 2;
        size_t bA = (size_t)(h * N + rA) * O + c0;
        size_t bB = (size_t)(h * N + rB) * O + c0;
#pragma unroll
        for (int nt = 0; nt < 8; ++nt) {
            *(uint32_t*)&g_Whb[bA + nt * 8] = b2u(__floats2bfloat162_rn(c[nt][0], c[nt][1]));
            *(uint32_t*)&g_Whb[bB + nt * 8] = b2u(__floats2bfloat162_rn(c[nt][2], c[nt][3]));
        }
    }
}

// ---------------- K1b: scores via GEMV s = x @ av, then exponentials ----------------
__global__ void k_scores1g(const float* __restrict__ x) {
    int gw = (blockIdx.x * blockDim.x + threadIdx.x) >> 5;  // node
    int lane = threadIdx.x & 31;
    const float4* xv = (const float4*)&x[(size_t)gw * F];
    float4 xr[4];
#pragma unroll
    for (int q = 0; q < 4; ++q) xr[q] = xv[q * 32 + lane];
#pragma unroll
    for (int h = 0; h < H; ++h) {
        const float4* a1 = (const float4*)&g_av[(h * 2) * F];
        const float4* a2 = (const float4*)&g_av[(h * 2 + 1) * F];
        float v1 = 0.f, v2 = 0.f;
#pragma unroll
        for (int q = 0; q < 4; ++q) {
            float4 w1 = a1[q * 32 + lane];
            float4 w2 = a2[q * 32 + lane];
            v1 += xr[q].x * w1.x + xr[q].y * w1.y + xr[q].z * w1.z + xr[q].w * w1.w;
            v2 += xr[q].x * w2.x + xr[q].y * w2.y + xr[q].z * w2.z + xr[q].w * w2.w;
        }
#pragma unroll
        for (int off = 16; off; off >>= 1) {
            v1 += __shfl_down_sync(0xffffffffu, v1, off);
            v2 += __shfl_down_sync(0xffffffffu, v2, off);
        }
        if (lane == 0) {
            g_E1pn[h * N + gw] = make_float2(expf(v1), expf(0.2f * v1));
            g_E2pn[h * N + gw] = make_float2(expf(v2), expf(0.2f * v2));
        }
    }
}

// ---------------- K2: layer-1 aggregate, direct-register P + mma.sync ----------------
// grid (N/64, H), 128 threads. B = Wh tile; A fragments computed in registers.
__global__ void __launch_bounds__(128) k_agg1_mma() {
    __shared__ __align__(16) uint16_t Whb_s[64 * 72];   // [j][c] bf16
    __shared__ uint2 e2s[32];                           // (e2p pair, e2n pair)

    int t = threadIdx.x;
    int w = t >> 5, lane = t & 31;
    int h = blockIdx.y, hN = h * N;
    int r0 = blockIdx.x * 64;

    int rA = r0 + w * 16 + (lane >> 2);
    int rB = rA + 8;
    int c0 = (lane & 3) * 2;
    int eix = lane & 3;

    float2 e1A = g_E1pn[hN + rA];
    float2 e1B = g_E1pn[hN + rB];
    uint32_t E1P_A = b2u(__float2bfloat162_rn(e1A.x));
    uint32_t E1N_A = b2u(__float2bfloat162_rn(e1A.y));
    uint32_t E1P_B = b2u(__float2bfloat162_rn(e1B.x));
    uint32_t E1N_B = b2u(__float2bfloat162_rn(e1B.y));

    float c[9][4];
#pragma unroll
    for (int i = 0; i < 9; ++i)
#pragma unroll
        for (int q = 0; q < 4; ++q) c[i][q] = 0.f;
    const uint32_t b_ones = 0x3F803F80u;

    int mrow = lane >> 3;
    int koff = (mrow >> 1) * 8;
    int brow8 = (mrow & 1) * 8 + (lane & 7);

    for (int tile = 0; tile < 64; ++tile) {
        int j0 = tile * 64;
        __syncthreads();   // previous MMA reads done before restage
        // stage Wh tile
#pragma unroll
        for (int it = 0; it < 4; ++it) {
            int u = t + it * 128;
            int j = u >> 3, c8 = (u & 7) * 8;
            uint4 v = *(const uint4*)&g_Whb[(size_t)(hN + j0 + j) * O + c8];
            *(uint4*)&Whb_s[j * 72 + c8] = v;
        }
        if (t < 32) {
            float4 e = *(const float4*)&g_E2pn[hN + j0 + 2 * t];
            uint2 pk;
            pk.x = b2u(__floats2bfloat162_rn(e.x, e.z));
            pk.y = b2u(__floats2bfloat162_rn(e.y, e.w));
            e2s[t] = pk;
        }
        uint32_t mA0 = g_mask[(size_t)rA * NW + (j0 >> 5)];
        uint32_t mA1 = g_mask[(size_t)rA * NW + (j0 >> 5) + 1];
        uint32_t mB0 = g_mask[(size_t)rB * NW + (j0 >> 5)];
        uint32_t mB1 = g_mask[(size_t)rB * NW + (j0 >> 5) + 1];
        __syncthreads();
#pragma unroll
        for (int ks = 0; ks < 4; ++ks) {
            uint2 ea = e2s[ks * 8 + eix];        // j = ks*16 + c0, +1
            uint2 eb = e2s[ks * 8 + 4 + eix];    // j = ks*16 + 8 + c0, +1
            uint32_t mwA = (ks < 2) ? mA0 : mA1;
            uint32_t mwB = (ks < 2) ? mB0 : mB1;
            int bit0 = (ks * 16 + c0) & 31;
            uint32_t a0 = wpair(E1P_A, E1N_A, ea, pairmask(mwA, bit0));
            uint32_t a1 = wpair(E1P_B, E1N_B, ea, pairmask(mwB, bit0));
            uint32_t a2 = wpair(E1P_A, E1N_A, eb, pairmask(mwA, bit0 + 8));
            uint32_t a3 = wpair(E1P_B, E1N_B, eb, pairmask(mwB, bit0 + 8));
#pragma unroll
            for (int nb = 0; nb < 4; ++nb) {
                uint32_t b0, b1, b2, b3;
                ldsm_x4t(b0, b1, b2, b3,
                         smem_u32(&Whb_s[(ks * 16 + brow8) * 72 + nb * 16 + koff]));
                mma_bf16(c[nb * 2],     a0, a1, a2, a3, b0, b1);
                mma_bf16(c[nb * 2 + 1], a0, a1, a2, a3, b2, b3);
            }
            mma_bf16(c[8], a0, a1, a2, a3, b_ones, b_ones);
        }
    }

    // epilogue: divide by den, ELU, store bf16 hcat
    {
        float invA = 1.f / c[8][0];
        float invB = 1.f / c[8][2];
        size_t bA = (size_t)rA * F + h * O + c0;
        size_t bB = (size_t)rB * F + h * O + c0;
#pragma unroll
        for (int nt = 0; nt < 8; ++nt) {
            float vA0 = elu(c[nt][0] * invA), vA1 = elu(c[nt][1] * invA);
            float vB0 = elu(c[nt][2] * invB), vB1 = elu(c[nt][3] * invB);
            *(uint32_t*)&g_hcatb[bA + nt * 8] = b2u(__floats2bfloat162_rn(vA0, vA1));
            *(uint32_t*)&g_hcatb[bB + nt * 8] = b2u(__floats2bfloat162_rn(vB0, vB1));
        }
    }
}

// ---------------- K3a: Who = hcat @ W_out via mma.sync (fp32 + bf16 out) ----------------
// grid N/64 = 64 blocks, 128 threads.
__global__ void __launch_bounds__(128) k_gemm2_mma(const float* __restrict__ Wout) {
    __shared__ __align__(16) uint16_t As[64 * 72];   // hcat [row][k] bf16
    __shared__ __align__(16) uint16_t Bs[64 * 24];   // Wout [k][c] bf16
    int t = threadIdx.x;
    int w = t >> 5, lane = t & 31;
    int r0 = blockIdx.x * 64;

    float c[2][4];
#pragma unroll
    for (int i = 0; i < 2; ++i)
#pragma unroll
        for (int q = 0; q < 4; ++q) c[i][q] = 0.f;

    int mrow = lane >> 3;
    int arow = w * 16 + (mrow & 1) * 8 + (lane & 7);
    int koff = (mrow >> 1) * 8;
    int brow8 = (mrow & 1) * 8 + (lane & 7);

    for (int kc = 0; kc < 8; ++kc) {
        int k0 = kc * 64;
        __syncthreads();
#pragma unroll
        for (int it = 0; it < 4; ++it) {
            int u = t + it * 128;
            int j = u >> 3, c8 = (u & 7) * 8;
            uint4 v = *(const uint4*)&g_hcatb[(size_t)(r0 + j) * F + k0 + c8];
            *(uint4*)&As[j * 72 + c8] = v;
        }
#pragma unroll
        for (int it = 0; it < 2; ++it) {
            int u = t + it * 128;                 // 0..255 float4 chunks
            int k = u >> 2, cq = (u & 3) * 4;
            float4 v = *(const float4*)&Wout[(size_t)(k0 + k) * C + cq];
            uint2 pk;
            pk.x = b2u(__floats2bfloat162_rn(v.x, v.y));
            pk.y = b2u(__floats2bfloat162_rn(v.z, v.w));
            *(uint2*)&Bs[k * 24 + cq] = pk;
        }
        __syncthreads();
#pragma unroll
        for (int ks = 0; ks < 4; ++ks) {
            uint32_t a0, a1, a2, a3;
            ldsm_x4(a0, a1, a2, a3, smem_u32(&As[arow * 72 + ks * 16 + koff]));
            uint32_t b0, b1, b2, b3;
            ldsm_x4t(b0, b1, b2, b3, smem_u32(&Bs[(ks * 16 + brow8) * 24 + koff]));
            mma_bf16(c[0], a0, a1, a2, a3, b0, b1);
            mma_bf16(c[1], a0, a1, a2, a3, b2, b3);
        }
    }
    {
        int rA = r0 + w * 16 + (lane >> 2);
        int rB = rA + 8;
        int c0 = (lane & 3) * 2;
        *(float2*)&g_Who[rA * C + c0]     = make_float2(c[0][0], c[0][1]);
        *(float2*)&g_Who[rA * C + 8 + c0] = make_float2(c[1][0], c[1][1]);
        *(float2*)&g_Who[rB * C + c0]     = make_float2(c[0][2], c[0][3]);
        *(float2*)&g_Who[rB * C + 8 + c0] = make_float2(c[1][2], c[1][3]);
        *(uint32_t*)&g_Whob[rA * C + c0]     = b2u(__floats2bfloat162_rn(c[0][0], c[0][1]));
        *(uint32_t*)&g_Whob[rA * C + 8 + c0] = b2u(__floats2bfloat162_rn(c[1][0], c[1][1]));
        *(uint32_t*)&g_Whob[rB * C + c0]     = b2u(__floats2bfloat162_rn(c[0][2], c[0][3]));
        *(uint32_t*)&g_Whob[rB * C + 8 + c0] = b2u(__floats2bfloat162_rn(c[1][2], c[1][3]));
    }
}

// ---------------- K3b: per-node scores + exponentials (layer 2) ----------------
__global__ void k_scores2(const float* __restrict__ aout) {
    int gw = (blockIdx.x * blockDim.x + threadIdx.x) >> 5;  // node id
    int lane = threadIdx.x & 31;
    float v1 = 0.f, v2 = 0.f;
    if (lane < C) {
        float w = g_Who[gw * C + lane];
        v1 = w * aout[lane];
        v2 = w * aout[C + lane];
    }
#pragma unroll
    for (int off = 8; off; off >>= 1) {
        v1 += __shfl_down_sync(0xffffffffu, v1, off);
        v2 += __shfl_down_sync(0xffffffffu, v2, off);
    }
    if (lane == 0) {
        g2_E1pn[gw] = make_float2(expf(v1), expf(0.2f * v1));
        g2_E2pn[gw] = make_float2(expf(v2), expf(0.2f * v2));
    }
}

// ---------------- K4: layer-2 aggregate, direct-register P + log_softmax ----------------
__global__ void __launch_bounds__(128) k_agg2_mma(float* __restrict__ out) {
    __shared__ __align__(16) uint16_t Who_s[64 * 24];
    __shared__ uint2 e2s[32];

    int t = threadIdx.x;
    int w = t >> 5, lane = t & 31;
    int r0 = blockIdx.x * 64;

    int rA = r0 + w * 16 + (lane >> 2);
    int rB = rA + 8;
    int c0 = (lane & 3) * 2;
    int eix = lane & 3;

    float2 e1A = g2_E1pn[rA];
    float2 e1B = g2_E1pn[rB];
    uint32_t E1P_A = b2u(__float2bfloat162_rn(e1A.x));
    uint32_t E1N_A = b2u(__float2bfloat162_rn(e1A.y));
    uint32_t E1P_B = b2u(__float2bfloat162_rn(e1B.x));
    uint32_t E1N_B = b2u(__float2bfloat162_rn(e1B.y));

    float c[3][4];
#pragma unroll
    for (int i = 0; i < 3; ++i)
#pragma unroll
        for (int q = 0; q < 4; ++q) c[i][q] = 0.f;
    const uint32_t b_ones = 0x3F803F80u;

    int mrow = lane >> 3;
    int koff = (mrow >> 1) * 8;
    int brow8 = (mrow & 1) * 8 + (lane & 7);

    for (int tile = 0; tile < 64; ++tile) {
        int j0 = tile * 64;
        __syncthreads();
        {   // stage Who tile: 64 rows x 16 cols bf16
            int j = t >> 1, half = t & 1;
            uint4 v = *(const uint4*)&g_Whob[(j0 + j) * C + half * 8];
            *(uint4*)&Who_s[j * 24 + half * 8] = v;
        }
        if (t < 32) {
            float4 e = *(const float4*)&g2_E2pn[j0 + 2 * t];
            uint2 pk;
            pk.x = b2u(__floats2bfloat162_rn(e.x, e.z));
            pk.y = b2u(__floats2bfloat162_rn(e.y, e.w));
            e2s[t] = pk;
        }
        uint32_t mA0 = g_mask[(size_t)rA * NW + (j0 >> 5)];
        uint32_t mA1 = g_mask[(size_t)rA * NW + (j0 >> 5) + 1];
        uint32_t mB0 = g_mask[(size_t)rB * NW + (j0 >> 5)];
        uint32_t mB1 = g_mask[(size_t)rB * NW + (j0 >> 5) + 1];
        __syncthreads();
#pragma unroll
        for (int ks = 0; ks < 4; ++ks) {
            uint2 ea = e2s[ks * 8 + eix];
            uint2 eb = e2s[ks * 8 + 4 + eix];
            uint32_t mwA = (ks < 2) ? mA0 : mA1;
            uint32_t mwB = (ks < 2) ? mB0 : mB1;
            int bit0 = (ks * 16 + c0) & 31;
            uint32_t a0 = wpair(E1P_A, E1N_A, ea, pairmask(mwA, bit0));
            uint32_t a1 = wpair(E1P_B, E1N_B, ea, pairmask(mwB, bit0));
            uint32_t a2 = wpair(E1P_A, E1N_A, eb, pairmask(mwA, bit0 + 8));
            uint32_t a3 = wpair(E1P_B, E1N_B, eb, pairmask(mwB, bit0 + 8));
            uint32_t b0, b1, b2, b3;
            ldsm_x4t(b0, b1, b2, b3,
                     smem_u32(&Who_s[(ks * 16 + brow8) * 24 + koff]));
            mma_bf16(c[0], a0, a1, a2, a3, b0, b1);
            mma_bf16(c[1], a0, a1, a2, a3, b2, b3);
            mma_bf16(c[2], a0, a1, a2, a3, b_ones, b_ones);
        }
    }

    // epilogue: divide, ELU, log_softmax over 16 cols (4 lanes per row)
    {
        float invA = 1.f / c[2][0];
        float invB = 1.f / c[2][2];
        float vA[4] = {elu(c[0][0] * invA), elu(c[0][1] * invA),
                       elu(c[1][0] * invA), elu(c[1][1] * invA)};
        float vB[4] = {elu(c[0][2] * invB), elu(c[0][3] * invB),
                       elu(c[1][2] * invB), elu(c[1][3] * invB)};
        float mxA = fmaxf(fmaxf(vA[0], vA[1]), fmaxf(vA[2], vA[3]));
        float mxB = fmaxf(fmaxf(vB[0], vB[1]), fmaxf(vB[2], vB[3]));
        mxA = fmaxf(mxA, __shfl_xor_sync(0xffffffffu, mxA, 1));
        mxA = fmaxf(mxA, __shfl_xor_sync(0xffffffffu, mxA, 2));
        mxB = fmaxf(mxB, __shfl_xor_sync(0xffffffffu, mxB, 1));
        mxB = fmaxf(mxB, __shfl_xor_sync(0xffffffffu, mxB, 2));
        float sA = expf(vA[0] - mxA) + expf(vA[1] - mxA) + expf(vA[2] - mxA) + expf(vA[3] - mxA);
        float sB = expf(vB[0] - mxB) + expf(vB[1] - mxB) + expf(vB[2] - mxB) + expf(vB[3] - mxB);
        sA += __shfl_xor_sync(0xffffffffu, sA, 1);
        sA += __shfl_xor_sync(0xffffffffu, sA, 2);
        sB += __shfl_xor_sync(0xffffffffu, sB, 1);
        sB += __shfl_xor_sync(0xffffffffu, sB, 2);
        float lseA = mxA + logf(sA);
        float lseB = mxB + logf(sB);
        *(float2*)&out[rA * C + c0]     = make_float2(vA[0] - lseA, vA[1] - lseA);
        *(float2*)&out[rA * C + 8 + c0] = make_float2(vA[2] - lseA, vA[3] - lseA);
        *(float2*)&out[rB * C + c0]     = make_float2(vB[0] - lseB, vB[1] - lseB);
        *(float2*)&out[rB * C + 8 + c0] = make_float2(vB[2] - lseB, vB[3] - lseB);
    }
}

// ---------------- launch ----------------
extern "C" void kernel_launch(void* const* d_in, const int* in_sizes, int n_in,
                              void* d_out, int out_size) {
    const float* x    = (const float*)d_in[0];
    const int*   adj  = (const int*)d_in[1];
    const float* W    = (const float*)d_in[2];
    const float* a    = (const float*)d_in[3];
    const float* Wout = (const float*)d_in[4];
    const float* aout = (const float*)d_in[5];
    float* out = (float*)d_out;

    k_pack<<<N * NW / 8, 256>>>(adj);
    k_prevec<<<32, 256>>>(W, a);
    k_gemm1_mma<<<dim3(N / 64, H), 128>>>(x, W);
    k_scores1g<<<N / 8, 256>>>(x);
    k_agg1_mma<<<dim3(N / 64, H), 128>>>();
    k_gemm2_mma<<<N / 64, 128>>>(Wout);
    k_scores2<<<N / 8, 256>>>(aout);
    k_agg2_mma<<<N / 64, 128>>>(out);
}

// round 11
// speedup vs baseline: 5.7826x; 1.4657x over previous
#include <cuda_runtime.h>
#include <cuda_bf16.h>
#include <math.h>
#include <cstdint>

#define N 4096
#define F 512
#define O 64
#define H 8
#define C 16
#define NW 128  // mask words per row (N/32)

// -------- scratch (static device globals; no allocation) --------
__device__ __align__(16) unsigned g_mask[N * NW];           // 2 MB bit-packed adjacency
__device__ __align__(16) __nv_bfloat16 g_xb[N * F];         // 4 MB bf16 x
__device__ __align__(16) __nv_bfloat16 g_Wb[H * F * O];     // 0.5 MB bf16 W
__device__ __align__(16) __nv_bfloat16 g_Woutb[F * C];      // bf16 Wout
__device__ __align__(16) __nv_bfloat16 g_Whb[H * N * O];    // 4 MB bf16 Wh
__device__ float g_av[2 * H * F];                            // W[h]@a1 / W[h]@a2
__device__ float2 g_E1pn[H * N];                             // (exp(v1), exp(.2 v1))
__device__ __align__(16) __nv_bfloat16 g_E2pb[H * N];        // bf16 exp(v2)
__device__ __align__(16) __nv_bfloat16 g_E2nb[H * N];        // bf16 exp(.2 v2)
__device__ __align__(16) __nv_bfloat16 g_hcatb[N * F];       // 4 MB bf16 hcat
__device__ float g_Who[N * C];
__device__ __align__(16) __nv_bfloat16 g_Whob[N * C];
__device__ float2 g2_E1pn[N];
__device__ __align__(16) __nv_bfloat16 g2_E2pb[N], g2_E2nb[N];

// -------- helpers --------
__device__ __forceinline__ uint32_t smem_u32(const void* p) {
    uint32_t a;
    asm("{ .reg .u64 t; cvta.to.shared.u64 t, %1; cvt.u32.u64 %0, t; }" : "=r"(a) : "l"(p));
    return a;
}
__device__ __forceinline__ void cp16(uint32_t s, const void* g) {
    asm volatile("cp.async.cg.shared.global [%0], [%1], 16;" :: "r"(s), "l"(g));
}
#define CP_COMMIT() asm volatile("cp.async.commit_group;" ::: "memory")
#define CP_WAIT(n)  asm volatile("cp.async.wait_group %0;" :: "n"(n) : "memory")

__device__ __forceinline__ void ldsm_x4(uint32_t& r0, uint32_t& r1, uint32_t& r2,
                                        uint32_t& r3, uint32_t addr) {
    asm volatile("ldmatrix.sync.aligned.m8n8.x4.shared.b16 {%0,%1,%2,%3}, [%4];"
                 : "=r"(r0), "=r"(r1), "=r"(r2), "=r"(r3) : "r"(addr));
}
__device__ __forceinline__ void ldsm_x4t(uint32_t& r0, uint32_t& r1, uint32_t& r2,
                                         uint32_t& r3, uint32_t addr) {
    asm volatile("ldmatrix.sync.aligned.m8n8.x4.trans.shared.b16 {%0,%1,%2,%3}, [%4];"
                 : "=r"(r0), "=r"(r1), "=r"(r2), "=r"(r3) : "r"(addr));
}
__device__ __forceinline__ void mma_bf16(float* c, uint32_t a0, uint32_t a1, uint32_t a2,
                                         uint32_t a3, uint32_t b0, uint32_t b1) {
    asm volatile(
        "mma.sync.aligned.m16n8k16.row.col.f32.bf16.bf16.f32 "
        "{%0,%1,%2,%3}, {%4,%5,%6,%7}, {%8,%9}, {%0,%1,%2,%3};"
        : "+f"(c[0]), "+f"(c[1]), "+f"(c[2]), "+f"(c[3])
        : "r"(a0), "r"(a1), "r"(a2), "r"(a3), "r"(b0), "r"(b1));
}
__device__ __forceinline__ uint32_t b2u(__nv_bfloat162 v) {
    return *reinterpret_cast<uint32_t*>(&v);
}
__device__ __forceinline__ __nv_bfloat162 u2b(uint32_t v) {
    return *reinterpret_cast<__nv_bfloat162*>(&v);
}
__device__ __forceinline__ float elu(float s) { return (s > 0.f) ? s : (expf(s) - 1.f); }

__device__ __forceinline__ uint32_t pairmask(uint32_t mword, int bit) {
    uint32_t m2 = (mword >> bit) & 3u;
    return ((m2 & 1u) ? 0xFFFFu : 0u) | ((m2 & 2u) ? 0xFFFF0000u : 0u);
}
// weight pair: max(e1p*e2p, e1n*e2n) masked; e2 pairs already bf16x2
__device__ __forceinline__ uint32_t wpair(uint32_t E1P, uint32_t E1N,
                                          uint32_t e2p, uint32_t e2n, uint32_t msk) {
    __nv_bfloat162 p = __hmul2(u2b(E1P), u2b(e2p));
    __nv_bfloat162 n = __hmul2(u2b(E1N), u2b(e2n));
    return b2u(__hmax2(p, n)) & msk;
}

// ---------------- K0: fused prep (pack + x/W/Wout -> bf16 + prevec) ----------------
#define PACKB 65536
#define XBB   2048
#define WBB   256
#define WOBB  8
#define PVB   32
__global__ void k_prep(const int* __restrict__ adj, const float* __restrict__ x,
                       const float* __restrict__ W, const float* __restrict__ Wout,
                       const float* __restrict__ a) {
    int b = blockIdx.x, t = threadIdx.x;
    if (b < PACKB) {
        int gt = b * 256 + t;
        int w = gt >> 5, lane = gt & 31;
        int i = w >> 7, jw = w & (NW - 1);
        int v = adj[(size_t)i * N + jw * 32 + lane];
        unsigned m = __ballot_sync(0xffffffffu, v > 0);
        if (lane == 0) g_mask[w] = m;
    } else if (b < PACKB + XBB) {
        int u = (b - PACKB) * 256 + t;
        float4 v = ((const float4*)x)[u];
        uint2 pk;
        pk.x = b2u(__floats2bfloat162_rn(v.x, v.y));
        pk.y = b2u(__floats2bfloat162_rn(v.z, v.w));
        ((uint2*)g_xb)[u] = pk;
    } else if (b < PACKB + XBB + WBB) {
        int u = (b - PACKB - XBB) * 256 + t;
        float4 v = ((const float4*)W)[u];
        uint2 pk;
        pk.x = b2u(__floats2bfloat162_rn(v.x, v.y));
        pk.y = b2u(__floats2bfloat162_rn(v.z, v.w));
        ((uint2*)g_Wb)[u] = pk;
    } else if (b < PACKB + XBB + WBB + WOBB) {
        int u = (b - PACKB - XBB - WBB) * 256 + t;
        float4 v = ((const float4*)Wout)[u];
        uint2 pk;
        pk.x = b2u(__floats2bfloat162_rn(v.x, v.y));
        pk.y = b2u(__floats2bfloat162_rn(v.z, v.w));
        ((uint2*)g_Woutb)[u] = pk;
    } else {
        int u = (b - PACKB - XBB - WBB - WOBB) * 256 + t;   // 0..8191
        int h = u >> 10, s = (u >> 9) & 1, f = u & 511;
        const float* wp = W + ((size_t)h * F + f) * O;
        const float* ap = a + h * 2 * O + s * O;
        float v = 0.f;
#pragma unroll
        for (int o = 0; o < O; ++o) v += wp[o] * ap[o];
        g_av[(h * 2 + s) * F + f] = v;
    }
}

// ---------------- K1: scores via GEMV s = x @ av, then exponentials ----------------
__global__ void k_scores1g(const float* __restrict__ x) {
    int gw = (blockIdx.x * blockDim.x + threadIdx.x) >> 5;  // node
    int lane = threadIdx.x & 31;
    const float4* xv = (const float4*)&x[(size_t)gw * F];
    float4 xr[4];
#pragma unroll
    for (int q = 0; q < 4; ++q) xr[q] = xv[q * 32 + lane];
#pragma unroll
    for (int h = 0; h < H; ++h) {
        const float4* a1 = (const float4*)&g_av[(h * 2) * F];
        const float4* a2 = (const float4*)&g_av[(h * 2 + 1) * F];
        float v1 = 0.f, v2 = 0.f;
#pragma unroll
        for (int q = 0; q < 4; ++q) {
            float4 w1 = a1[q * 32 + lane];
            float4 w2 = a2[q * 32 + lane];
            v1 += xr[q].x * w1.x + xr[q].y * w1.y + xr[q].z * w1.z + xr[q].w * w1.w;
            v2 += xr[q].x * w2.x + xr[q].y * w2.y + xr[q].z * w2.z + xr[q].w * w2.w;
        }
#pragma unroll
        for (int off = 16; off; off >>= 1) {
            v1 += __shfl_down_sync(0xffffffffu, v1, off);
            v2 += __shfl_down_sync(0xffffffffu, v2, off);
        }
        if (lane == 0) {
            g_E1pn[h * N + gw] = make_float2(expf(v1), expf(0.2f * v1));
            g_E2pb[h * N + gw] = __float2bfloat16(expf(v2));
            g_E2nb[h * N + gw] = __float2bfloat16(expf(0.2f * v2));
        }
    }
}

// ---------------- K2: Whb[h] = bf16(xb @ Wb[h]), cp.async double-buffered ----------------
__global__ void __launch_bounds__(128) k_gemm1_mma() {
    __shared__ __align__(16) uint16_t Xs[2][64 * 72];
    __shared__ __align__(16) uint16_t Ws[2][64 * 72];
    int t = threadIdx.x;
    int w = t >> 5, lane = t & 31;
    int h = blockIdx.y;
    int r0 = blockIdx.x * 64;

    float c[8][4];
#pragma unroll
    for (int i = 0; i < 8; ++i)
#pragma unroll
        for (int q = 0; q < 4; ++q) c[i][q] = 0.f;

    int mrow = lane >> 3;
    int arow = w * 16 + (mrow & 1) * 8 + (lane & 7);
    int koff = (mrow >> 1) * 8;
    int brow8 = (mrow & 1) * 8 + (lane & 7);

    // stage chunk kc into buffer bb
#define G1_STAGE(kc, bb)                                                       \
    do {                                                                       \
        int k0_ = (kc) * 64;                                                   \
        _Pragma("unroll")                                                      \
        for (int it = 0; it < 4; ++it) {                                       \
            int u = t + it * 128, j = u >> 3, c8 = (u & 7) * 8;                \
            cp16(smem_u32(&Xs[bb][j * 72 + c8]),                               \
                 &g_xb[(size_t)(r0 + j) * F + k0_ + c8]);                      \
            cp16(smem_u32(&Ws[bb][j * 72 + c8]),                               \
                 &g_Wb[((size_t)h * F + k0_ + j) * O + c8]);                   \
        }                                                                      \
        CP_COMMIT();                                                           \
    } while (0)

    G1_STAGE(0, 0);
    for (int kc = 0; kc < 8; ++kc) {
        int bb = kc & 1;
        if (kc < 7) { G1_STAGE(kc + 1, bb ^ 1); CP_WAIT(1); }
        else        { CP_WAIT(0); }
        __syncthreads();
#pragma unroll
        for (int ks = 0; ks < 4; ++ks) {
            uint32_t a0, a1, a2, a3;
            ldsm_x4(a0, a1, a2, a3, smem_u32(&Xs[bb][arow * 72 + ks * 16 + koff]));
#pragma unroll
            for (int nb = 0; nb < 4; ++nb) {
                uint32_t b0, b1, b2, b3;
                ldsm_x4t(b0, b1, b2, b3,
                         smem_u32(&Ws[bb][(ks * 16 + brow8) * 72 + nb * 16 + koff]));
                mma_bf16(c[nb * 2],     a0, a1, a2, a3, b0, b1);
                mma_bf16(c[nb * 2 + 1], a0, a1, a2, a3, b2, b3);
            }
        }
        __syncthreads();
    }
    {
        int rA = r0 + w * 16 + (lane >> 2);
        int rB = rA + 8;
        int c0 = (lane & 3) * 2;
        size_t bA = (size_t)(h * N + rA) * O + c0;
        size_t bB = (size_t)(h * N + rB) * O + c0;
#pragma unroll
        for (int nt = 0; nt < 8; ++nt) {
            *(uint32_t*)&g_Whb[bA + nt * 8] = b2u(__floats2bfloat162_rn(c[nt][0], c[nt][1]));
            *(uint32_t*)&g_Whb[bB + nt * 8] = b2u(__floats2bfloat162_rn(c[nt][2], c[nt][3]));
        }
    }
#undef G1_STAGE
}

// ---------------- K3: layer-1 aggregate, direct-register P + cp.async pipeline ----------------
__global__ void __launch_bounds__(128) k_agg1_mma() {
    __shared__ __align__(16) uint16_t Whb_s[2][64 * 72];
    __shared__ __align__(16) uint16_t e2p_s[2][64];
    __shared__ __align__(16) uint16_t e2n_s[2][64];

    int t = threadIdx.x;
    int w = t >> 5, lane = t & 31;
    int h = blockIdx.y, hN = h * N;
    int r0 = blockIdx.x * 64;

    int rA = r0 + w * 16 + (lane >> 2);
    int rB = rA + 8;
    int c0 = (lane & 3) * 2;
    int eix = lane & 3;

    float2 e1A = g_E1pn[hN + rA];
    float2 e1B = g_E1pn[hN + rB];
    uint32_t E1P_A = b2u(__float2bfloat162_rn(e1A.x));
    uint32_t E1N_A = b2u(__float2bfloat162_rn(e1A.y));
    uint32_t E1P_B = b2u(__float2bfloat162_rn(e1B.x));
    uint32_t E1N_B = b2u(__float2bfloat162_rn(e1B.y));

    float c[9][4];
#pragma unroll
    for (int i = 0; i < 9; ++i)
#pragma unroll
        for (int q = 0; q < 4; ++q) c[i][q] = 0.f;
    const uint32_t b_ones = 0x3F803F80u;

    int mrow = lane >> 3;
    int koff = (mrow >> 1) * 8;
    int brow8 = (mrow & 1) * 8 + (lane & 7);

#define A1_STAGE(tile, bb)                                                     \
    do {                                                                       \
        int j0_ = (tile) * 64;                                                 \
        _Pragma("unroll")                                                      \
        for (int it = 0; it < 4; ++it) {                                       \
            int u = t + it * 128, j = u >> 3, c8 = (u & 7) * 8;                \
            cp16(smem_u32(&Whb_s[bb][j * 72 + c8]),                            \
                 &g_Whb[(size_t)(hN + j0_ + j) * O + c8]);                     \
        }                                                                      \
        if (t < 8)       cp16(smem_u32(&e2p_s[bb][t * 8]), &g_E2pb[hN + j0_ + t * 8]); \
        else if (t < 16) cp16(smem_u32(&e2n_s[bb][(t - 8) * 8]), &g_E2nb[hN + j0_ + (t - 8) * 8]); \
        CP_COMMIT();                                                           \
    } while (0)

    A1_STAGE(0, 0);
    uint32_t mA0 = g_mask[(size_t)rA * NW];
    uint32_t mA1 = g_mask[(size_t)rA * NW + 1];
    uint32_t mB0 = g_mask[(size_t)rB * NW];
    uint32_t mB1 = g_mask[(size_t)rB * NW + 1];

    for (int tile = 0; tile < 64; ++tile) {
        int bb = tile & 1;
        uint32_t nA0, nA1, nB0, nB1;
        if (tile < 63) {
            A1_STAGE(tile + 1, bb ^ 1);
            int wj = (tile + 1) * 2;
            nA0 = g_mask[(size_t)rA * NW + wj];
            nA1 = g_mask[(size_t)rA * NW + wj + 1];
            nB0 = g_mask[(size_t)rB * NW + wj];
            nB1 = g_mask[(size_t)rB * NW + wj + 1];
            CP_WAIT(1);
        } else {
            nA0 = nA1 = nB0 = nB1 = 0;
            CP_WAIT(0);
        }
        __syncthreads();
#pragma unroll
        for (int ks = 0; ks < 4; ++ks) {
            uint32_t eaP = *(const uint32_t*)&e2p_s[bb][(ks * 8 + eix) * 2];
            uint32_t eaN = *(const uint32_t*)&e2n_s[bb][(ks * 8 + eix) * 2];
            uint32_t ebP = *(const uint32_t*)&e2p_s[bb][(ks * 8 + 4 + eix) * 2];
            uint32_t ebN = *(const uint32_t*)&e2n_s[bb][(ks * 8 + 4 + eix) * 2];
            uint32_t mwA = (ks < 2) ? mA0 : mA1;
            uint32_t mwB = (ks < 2) ? mB0 : mB1;
            int bit0 = (ks * 16 + c0) & 31;
            uint32_t a0 = wpair(E1P_A, E1N_A, eaP, eaN, pairmask(mwA, bit0));
            uint32_t a1 = wpair(E1P_B, E1N_B, eaP, eaN, pairmask(mwB, bit0));
            uint32_t a2 = wpair(E1P_A, E1N_A, ebP, ebN, pairmask(mwA, bit0 + 8));
            uint32_t a3 = wpair(E1P_B, E1N_B, ebP, ebN, pairmask(mwB, bit0 + 8));
#pragma unroll
            for (int nb = 0; nb < 4; ++nb) {
                uint32_t b0, b1, b2, b3;
                ldsm_x4t(b0, b1, b2, b3,
                         smem_u32(&Whb_s[bb][(ks * 16 + brow8) * 72 + nb * 16 + koff]));
                mma_bf16(c[nb * 2],     a0, a1, a2, a3, b0, b1);
                mma_bf16(c[nb * 2 + 1], a0, a1, a2, a3, b2, b3);
            }
            mma_bf16(c[8], a0, a1, a2, a3, b_ones, b_ones);
        }
        __syncthreads();
        mA0 = nA0; mA1 = nA1; mB0 = nB0; mB1 = nB1;
    }

    // epilogue: divide by den, ELU, store bf16 hcat
    {
        float invA = 1.f / c[8][0];
        float invB = 1.f / c[8][2];
        size_t bA = (size_t)rA * F + h * O + c0;
        size_t bB = (size_t)rB * F + h * O + c0;
#pragma unroll
        for (int nt = 0; nt < 8; ++nt) {
            float vA0 = elu(c[nt][0] * invA), vA1 = elu(c[nt][1] * invA);
            float vB0 = elu(c[nt][2] * invB), vB1 = elu(c[nt][3] * invB);
            *(uint32_t*)&g_hcatb[bA + nt * 8] = b2u(__floats2bfloat162_rn(vA0, vA1));
            *(uint32_t*)&g_hcatb[bB + nt * 8] = b2u(__floats2bfloat162_rn(vB0, vB1));
        }
    }
#undef A1_STAGE
}

// ---------------- K4: Who = hcatb @ Woutb, cp.async double-buffered ----------------
__global__ void __launch_bounds__(128) k_gemm2_mma() {
    __shared__ __align__(16) uint16_t As[2][64 * 72];
    __shared__ __align__(16) uint16_t Bs[2][64 * 24];
    int t = threadIdx.x;
    int w = t >> 5, lane = t & 31;
    int r0 = blockIdx.x * 64;

    float c[2][4];
#pragma unroll
    for (int i = 0; i < 2; ++i)
#pragma unroll
        for (int q = 0; q < 4; ++q) c[i][q] = 0.f;

    int mrow = lane >> 3;
    int arow = w * 16 + (mrow & 1) * 8 + (lane & 7);
    int koff = (mrow >> 1) * 8;
    int brow8 = (mrow & 1) * 8 + (lane & 7);

#define G2_STAGE(kc, bb)                                                       \
    do {                                                                       \
        int k0_ = (kc) * 64;                                                   \
        _Pragma("unroll")                                                      \
        for (int it = 0; it < 4; ++it) {                                       \
            int u = t + it * 128, j = u >> 3, c8 = (u & 7) * 8;                \
            cp16(smem_u32(&As[bb][j * 72 + c8]),                               \
                 &g_hcatb[(size_t)(r0 + j) * F + k0_ + c8]);                   \
        }                                                                      \
        { int k = t >> 1, cq = (t & 1) * 8;                                    \
          cp16(smem_u32(&Bs[bb][k * 24 + cq]),                                 \
               &g_Woutb[(size_t)(k0_ + k) * C + cq]); }                        \
        CP_COMMIT();                                                           \
    } while (0)

    G2_STAGE(0, 0);
    for (int kc = 0; kc < 8; ++kc) {
        int bb = kc & 1;
        if (kc < 7) { G2_STAGE(kc + 1, bb ^ 1); CP_WAIT(1); }
        else        { CP_WAIT(0); }
        __syncthreads();
#pragma unroll
        for (int ks = 0; ks < 4; ++ks) {
            uint32_t a0, a1, a2, a3;
            ldsm_x4(a0, a1, a2, a3, smem_u32(&As[bb][arow * 72 + ks * 16 + koff]));
            uint32_t b0, b1, b2, b3;
            ldsm_x4t(b0, b1, b2, b3, smem_u32(&Bs[bb][(ks * 16 + brow8) * 24 + koff]));
            mma_bf16(c[0], a0, a1, a2, a3, b0, b1);
            mma_bf16(c[1], a0, a1, a2, a3, b2, b3);
        }
        __syncthreads();
    }
    {
        int rA = r0 + w * 16 + (lane >> 2);
        int rB = rA + 8;
        int c0 = (lane & 3) * 2;
        *(float2*)&g_Who[rA * C + c0]     = make_float2(c[0][0], c[0][1]);
        *(float2*)&g_Who[rA * C + 8 + c0] = make_float2(c[1][0], c[1][1]);
        *(float2*)&g_Who[rB * C + c0]     = make_float2(c[0][2], c[0][3]);
        *(float2*)&g_Who[rB * C + 8 + c0] = make_float2(c[1][2], c[1][3]);
        *(uint32_t*)&g_Whob[rA * C + c0]     = b2u(__floats2bfloat162_rn(c[0][0], c[0][1]));
        *(uint32_t*)&g_Whob[rA * C + 8 + c0] = b2u(__floats2bfloat162_rn(c[1][0], c[1][1]));
        *(uint32_t*)&g_Whob[rB * C + c0]     = b2u(__floats2bfloat162_rn(c[0][2], c[0][3]));
        *(uint32_t*)&g_Whob[rB * C + 8 + c0] = b2u(__floats2bfloat162_rn(c[1][2], c[1][3]));
    }
#undef G2_STAGE
}

// ---------------- K5: layer-2 scores + exponentials ----------------
__global__ void k_scores2(const float* __restrict__ aout) {
    int gw = (blockIdx.x * blockDim.x + threadIdx.x) >> 5;  // node id
    int lane = threadIdx.x & 31;
    float v1 = 0.f, v2 = 0.f;
    if (lane < C) {
        float w = g_Who[gw * C + lane];
        v1 = w * aout[lane];
        v2 = w * aout[C + lane];
    }
#pragma unroll
    for (int off = 8; off; off >>= 1) {
        v1 += __shfl_down_sync(0xffffffffu, v1, off);
        v2 += __shfl_down_sync(0xffffffffu, v2, off);
    }
    if (lane == 0) {
        g2_E1pn[gw] = make_float2(expf(v1), expf(0.2f * v1));
        g2_E2pb[gw] = __float2bfloat16(expf(v2));
        g2_E2nb[gw] = __float2bfloat16(expf(0.2f * v2));
    }
}

// ---------------- K6: layer-2 aggregate + log_softmax, cp.async pipeline ----------------
__global__ void __launch_bounds__(128) k_agg2_mma(float* __restrict__ out) {
    __shared__ __align__(16) uint16_t Who_s[2][64 * 24];
    __shared__ __align__(16) uint16_t e2p_s[2][64];
    __shared__ __align__(16) uint16_t e2n_s[2][64];

    int t = threadIdx.x;
    int w = t >> 5, lane = t & 31;
    int r0 = blockIdx.x * 64;

    int rA = r0 + w * 16 + (lane >> 2);
    int rB = rA + 8;
    int c0 = (lane & 3) * 2;
    int eix = lane & 3;

    float2 e1A = g2_E1pn[rA];
    float2 e1B = g2_E1pn[rB];
    uint32_t E1P_A = b2u(__float2bfloat162_rn(e1A.x));
    uint32_t E1N_A = b2u(__float2bfloat162_rn(e1A.y));
    uint32_t E1P_B = b2u(__float2bfloat162_rn(e1B.x));
    uint32_t E1N_B = b2u(__float2bfloat162_rn(e1B.y));

    float c[3][4];
#pragma unroll
    for (int i = 0; i < 3; ++i)
#pragma unroll
        for (int q = 0; q < 4; ++q) c[i][q] = 0.f;
    const uint32_t b_ones = 0x3F803F80u;

    int mrow = lane >> 3;
    int koff = (mrow >> 1) * 8;
    int brow8 = (mrow & 1) * 8 + (lane & 7);

#define A2_STAGE(tile, bb)                                                     \
    do {                                                                       \
        int j0_ = (tile) * 64;                                                 \
        { int j = t >> 1, cq = (t & 1) * 8;                                    \
          cp16(smem_u32(&Who_s[bb][j * 24 + cq]),                              \
               &g_Whob[(size_t)(j0_ + j) * C + cq]); }                         \
        if (t < 8)       cp16(smem_u32(&e2p_s[bb][t * 8]), &g2_E2pb[j0_ + t * 8]); \
        else if (t < 16) cp16(smem_u32(&e2n_s[bb][(t - 8) * 8]), &g2_E2nb[j0_ + (t - 8) * 8]); \
        CP_COMMIT();                                                           \
    } while (0)

    A2_STAGE(0, 0);
    uint32_t mA0 = g_mask[(size_t)rA * NW];
    uint32_t mA1 = g_mask[(size_t)rA * NW + 1];
    uint32_t mB0 = g_mask[(size_t)rB * NW];
    uint32_t mB1 = g_mask[(size_t)rB * NW + 1];

    for (int tile = 0; tile < 64; ++tile) {
        int bb = tile & 1;
        uint32_t nA0, nA1, nB0, nB1;
        if (tile < 63) {
            A2_STAGE(tile + 1, bb ^ 1);
            int wj = (tile + 1) * 2;
            nA0 = g_mask[(size_t)rA * NW + wj];
            nA1 = g_mask[(size_t)rA * NW + wj + 1];
            nB0 = g_mask[(size_t)rB * NW + wj];
            nB1 = g_mask[(size_t)rB * NW + wj + 1];
            CP_WAIT(1);
        } else {
            nA0 = nA1 = nB0 = nB1 = 0;
            CP_WAIT(0);
        }
        __syncthreads();
#pragma unroll
        for (int ks = 0; ks < 4; ++ks) {
            uint32_t eaP = *(const uint32_t*)&e2p_s[bb][(ks * 8 + eix) * 2];
            uint32_t eaN = *(const uint32_t*)&e2n_s[bb][(ks * 8 + eix) * 2];
            uint32_t ebP = *(const uint32_t*)&e2p_s[bb][(ks * 8 + 4 + eix) * 2];
            uint32_t ebN = *(const uint32_t*)&e2n_s[bb][(ks * 8 + 4 + eix) * 2];
            uint32_t mwA = (ks < 2) ? mA0 : mA1;
            uint32_t mwB = (ks < 2) ? mB0 : mB1;
            int bit0 = (ks * 16 + c0) & 31;
            uint32_t a0 = wpair(E1P_A, E1N_A, eaP, eaN, pairmask(mwA, bit0));
            uint32_t a1 = wpair(E1P_B, E1N_B, eaP, eaN, pairmask(mwB, bit0));
            uint32_t a2 = wpair(E1P_A, E1N_A, ebP, ebN, pairmask(mwA, bit0 + 8));
            uint32_t a3 = wpair(E1P_B, E1N_B, ebP, ebN, pairmask(mwB, bit0 + 8));
            uint32_t b0, b1, b2, b3;
            ldsm_x4t(b0, b1, b2, b3,
                     smem_u32(&Who_s[bb][(ks * 16 + brow8) * 24 + koff]));
            mma_bf16(c[0], a0, a1, a2, a3, b0, b1);
            mma_bf16(c[1], a0, a1, a2, a3, b2, b3);
            mma_bf16(c[2], a0, a1, a2, a3, b_ones, b_ones);
        }
        __syncthreads();
        mA0 = nA0; mA1 = nA1; mB0 = nB0; mB1 = nB1;
    }

    // epilogue: divide, ELU, log_softmax over 16 cols (4 lanes per row)
    {
        float invA = 1.f / c[2][0];
        float invB = 1.f / c[2][2];
        float vA[4] = {elu(c[0][0] * invA), elu(c[0][1] * invA),
                       elu(c[1][0] * invA), elu(c[1][1] * invA)};
        float vB[4] = {elu(c[0][2] * invB), elu(c[0][3] * invB),
                       elu(c[1][2] * invB), elu(c[1][3] * invB)};
        float mxA = fmaxf(fmaxf(vA[0], vA[1]), fmaxf(vA[2], vA[3]));
        float mxB = fmaxf(fmaxf(vB[0], vB[1]), fmaxf(vB[2], vB[3]));
        mxA = fmaxf(mxA, __shfl_xor_sync(0xffffffffu, mxA, 1));
        mxA = fmaxf(mxA, __shfl_xor_sync(0xffffffffu, mxA, 2));
        mxB = fmaxf(mxB, __shfl_xor_sync(0xffffffffu, mxB, 1));
        mxB = fmaxf(mxB, __shfl_xor_sync(0xffffffffu, mxB, 2));
        float sA = expf(vA[0] - mxA) + expf(vA[1] - mxA) + expf(vA[2] - mxA) + expf(vA[3] - mxA);
        float sB = expf(vB[0] - mxB) + expf(vB[1] - mxB) + expf(vB[2] - mxB) + expf(vB[3] - mxB);
        sA += __shfl_xor_sync(0xffffffffu, sA, 1);
        sA += __shfl_xor_sync(0xffffffffu, sA, 2);
        sB += __shfl_xor_sync(0xffffffffu, sB, 1);
        sB += __shfl_xor_sync(0xffffffffu, sB, 2);
        float lseA = mxA + logf(sA);
        float lseB = mxB + logf(sB);
        *(float2*)&out[rA * C + c0]     = make_float2(vA[0] - lseA, vA[1] - lseA);
        *(float2*)&out[rA * C + 8 + c0] = make_float2(vA[2] - lseA, vA[3] - lseA);
        *(float2*)&out[rB * C + c0]     = make_float2(vB[0] - lseB, vB[1] - lseB);
        *(float2*)&out[rB * C + 8 + c0] = make_float2(vB[2] - lseB, vB[3] - lseB);
    }
#undef A2_STAGE
}

// ---------------- launch ----------------
extern "C" void kernel_launch(void* const* d_in, const int* in_sizes, int n_in,
                              void* d_out, int out_size) {
    const float* x    = (const float*)d_in[0];
    const int*   adj  = (const int*)d_in[1];
    const float* W    = (const float*)d_in[2];
    const float* a    = (const float*)d_in[3];
    const float* Wout = (const float*)d_in[4];
    const float* aout = (const float*)d_in[5];
    float* out = (float*)d_out;

    k_prep<<<PACKB + XBB + WBB + WOBB + PVB, 256>>>(adj, x, W, Wout, a);
    k_scores1g<<<N / 8, 256>>>(x);
    k_gemm1_mma<<<dim3(N / 64, H), 128>>>();
    k_agg1_mma<<<dim3(N / 64, H), 128>>>();     // 4th launch -> profiled
    k_gemm2_mma<<<N / 64, 128>>>();
    k_scores2<<<N / 8, 256>>>(aout);
    k_agg2_mma<<<N / 64, 128>>>(out);
}